// round 16
// baseline (speedup 1.0000x reference)
#include <cuda_runtime.h>
#include <cuda_bf16.h>

#define EPS_CLAMP 1e-4f
#define BLK 128
#define WPB (BLK / 32)
#define MAXBLOCKS 512   // 2048 warps; 8192 tiles -> exactly 4 tiles/warp

// Symmetric 3x3 packed [00,01,02,11,12,22]; u = a*b for commuting symmetric.
__device__ __forceinline__ void symprod(const float a[6], const float b[6],
                                        float u[6]) {
    u[0] = a[0]*b[0] + a[1]*b[1] + a[2]*b[2];
    u[1] = a[0]*b[1] + a[1]*b[3] + a[2]*b[4];
    u[2] = a[0]*b[2] + a[1]*b[4] + a[2]*b[5];
    u[3] = a[1]*b[1] + a[3]*b[3] + a[4]*b[4];
    u[4] = a[1]*b[2] + a[3]*b[4] + a[4]*b[5];
    u[5] = a[2]*b[2] + a[4]*b[4] + a[5]*b[5];
}

// ---------------------------------------------------------------------------
// Single-launch, persistent, warp-autonomous SPDNet decoder.
// exp(A) via Cayley-Hamilton coefficient space: S=A/16; every S^k = aS^2+bS+cI,
// Taylor-8 and 4 squarings run as SCALAR (a,b,c) recurrences (3-15 FMA each
// instead of 18 vector FMA) -> ~150 FMA/item for the whole exp.
// X9 = M (X3 - EPS I) M^T + EPS I  (telescoped constant, folded).
// ---------------------------------------------------------------------------
__global__ void __launch_bounds__(BLK)
spd_main_kernel(const float* __restrict__ vech,
                const float* __restrict__ W1,
                const float* __restrict__ W2,
                const float* __restrict__ W3,
                float* __restrict__ out, int B) {
    __shared__ __align__(16) float stage[WPB][32 * 81];  // 41472 B

    const int w    = threadIdx.x >> 5;
    const int lane = threadIdx.x & 31;
    const int nTiles = (B + 31) >> 5;
    const int warpStride = gridDim.x * WPB;
    int tile = blockIdx.x * WPB + w;

    float* const slice = stage[w];

    // ---- fire first prefetch ASAP ----
    float pf[6];
    bool pfFull = false;
    if (tile < nTiles) {
        const int i0 = tile << 5;
        pfFull = (B - i0 >= 32);
        if (pfFull) {
            #pragma unroll
            for (int k = 0; k < 6; k++)
                pf[k] = vech[(size_t)i0 * 6 + k * 32 + lane];
        }
    }

    // ---- per-warp M = W3 (W2 W1): uniform, overlaps prefetch latency ----
    float M[27];
    {
        float w21[21];
        #pragma unroll
        for (int a = 0; a < 7; a++) {
            #pragma unroll
            for (int k = 0; k < 3; k++) {
                float s = 0.f;
                #pragma unroll
                for (int b = 0; b < 5; b++) s += W2[a*5+b] * W1[b*3+k];
                w21[a*3+k] = s;
            }
        }
        #pragma unroll
        for (int r = 0; r < 9; r++) {
            #pragma unroll
            for (int k = 0; k < 3; k++) {
                float s = 0.f;
                #pragma unroll
                for (int a = 0; a < 7; a++) s += W3[r*7+a] * w21[a*3+k];
                M[r*3+k] = s;
            }
        }
    }

    // ---- persistent tile loop ----
    while (tile < nTiles) {
        const int wItem0 = tile << 5;
        const int wn = min(32, B - wItem0);
        const int nextTile = tile + warpStride;

        if (pfFull) {
            #pragma unroll
            for (int k = 0; k < 6; k++)
                slice[k * 32 + lane] = pf[k];
        } else {
            for (int idx = lane; idx < wn * 6; idx += 32)
                slice[idx] = vech[(size_t)wItem0 * 6 + idx];
        }
        __syncwarp();

        float v[6];
        {
            const float2* s2 = reinterpret_cast<const float2*>(slice);
            float2 p0 = s2[lane * 3 + 0];
            float2 p1 = s2[lane * 3 + 1];
            float2 p2 = s2[lane * 3 + 2];
            v[0] = p0.x; v[1] = p0.y; v[2] = p1.x;
            v[3] = p1.y; v[4] = p2.x; v[5] = p2.y;
        }
        __syncwarp();  // slice reads done; free for output staging

        // prefetch NEXT tile (hides under math + stores)
        pfFull = false;
        if (nextTile < nTiles) {
            const int ni0 = nextTile << 5;
            pfFull = (B - ni0 >= 32);
            if (pfFull) {
                #pragma unroll
                for (int k = 0; k < 6; k++)
                    pf[k] = vech[(size_t)ni0 * 6 + k * 32 + lane];
            }
        }

        if (lane < wn) {
            // ---- S = A/16; S2 = S*S ----
            float S[6];
            #pragma unroll
            for (int i = 0; i < 6; i++) S[i] = v[i] * 0.0625f;
            float S2[6];
            symprod(S, S, S2);

            // ---- invariants: S^3 = p S^2 - q S + r I ----
            const float p = S[0] + S[3] + S[5];
            const float t2 = S2[0] + S2[3] + S2[5];
            const float q = 0.5f * (p * p - t2);
            const float r = S[0] * (S[3]*S[5] - S[4]*S[4])
                          - S[1] * (S[1]*S[5] - S[4]*S[2])
                          + S[2] * (S[1]*S[4] - S[3]*S[2]);

            // ---- Taylor-8 of exp(S) in (a,b,c) basis: 3+3 FMA per term ----
            // E = ea*S2 + eb*S + ec*I ; S^k tracked as (aa,bb,cc)
            float aa = 1.0f, bb = 0.0f, cc = 0.0f;   // S^2
            float ea = 0.5f, eb = 1.0f, ec = 1.0f;   // I + S + S^2/2
            const float invf[6] = { 1.6666667e-1f, 4.1666667e-2f,
                                    8.3333333e-3f, 1.3888889e-3f,
                                    1.9841270e-4f, 2.4801587e-5f }; // 1/3!..1/8!
            #pragma unroll
            for (int k = 0; k < 6; k++) {
                const float na = bb + p * aa;
                const float nb = cc - q * aa;
                const float nc = r * aa;
                aa = na; bb = nb; cc = nc;
                ea += aa * invf[k]; eb += bb * invf[k]; ec += cc * invf[k];
            }

            // ---- 4 squarings in coefficient space ----
            // S^4 = u S^2 + w S + z I
            const float u = p * p - q, wq = r - p * q, z = p * r;
            #pragma unroll
            for (int sq = 0; sq < 4; sq++) {
                const float A2 = ea * ea;
                const float AB2 = 2.0f * ea * eb;
                const float B2 = eb * eb;
                const float na = A2 * u + AB2 * p + (B2 + 2.0f * ea * ec);
                const float nb = A2 * wq - AB2 * q + 2.0f * eb * ec;
                const float nc = A2 * z + AB2 * r + ec * ec;
                ea = na; eb = nb; ec = nc;
            }

            // ---- X' = exp(A) - EPS*I = ea*S2 + eb*S + (ec-EPS)*I ----
            const float cd = ec - EPS_CLAMP;
            const float x00 = ea * S2[0] + eb * S[0] + cd;
            const float x01 = ea * S2[1] + eb * S[1];
            const float x02 = ea * S2[2] + eb * S[2];
            const float x11 = ea * S2[3] + eb * S[3] + cd;
            const float x12 = ea * S2[4] + eb * S[4];
            const float x22 = ea * S2[5] + eb * S[5] + cd;

            // ---- X9 = M X' M^T + EPS*I, row-fused ----
            float* st = &slice[lane * 81];
            #pragma unroll
            for (int rr = 0; rr < 9; rr++) {
                const float m0 = M[rr*3+0], m1 = M[rr*3+1], m2 = M[rr*3+2];
                const float y0 = m0 * x00 + m1 * x01 + m2 * x02;
                const float y1 = m0 * x01 + m1 * x11 + m2 * x12;
                const float y2 = m0 * x02 + m1 * x12 + m2 * x22;
                #pragma unroll
                for (int ccn = rr; ccn < 9; ccn++) {
                    float val = y0 * M[ccn*3+0] + y1 * M[ccn*3+1] + y2 * M[ccn*3+2];
                    if (ccn == rr) val += EPS_CLAMP;
                    st[rr*9+ccn] = val;
                    st[ccn*9+rr] = val;
                }
            }
        }
        __syncwarp();

        // ---- coalesced copy slice -> gmem ----
        if (wn == 32) {
            float4* o4 = reinterpret_cast<float4*>(out + (size_t)wItem0 * 81);
            const float4* s4 = reinterpret_cast<const float4*>(slice);
            #pragma unroll 7
            for (int idx = lane; idx < (32 * 81) / 4; idx += 32)
                o4[idx] = s4[idx];
        } else if (wn > 0) {
            float* ob = out + (size_t)wItem0 * 81;
            for (int idx = lane; idx < wn * 81; idx += 32)
                ob[idx] = slice[idx];
        }

        tile = nextTile;
        __syncwarp();  // copy LDS ordered before next stage STS (WAR)
    }
}

// ---------------------------------------------------------------------------
extern "C" void kernel_launch(void* const* d_in, const int* in_sizes, int n_in,
                              void* d_out, int out_size) {
    const float* vech = nullptr;
    const float* W1 = nullptr;
    const float* W2 = nullptr;
    const float* W3 = nullptr;
    int vech_elems = 0;
    for (int i = 0; i < n_in; i++) {
        int sz = in_sizes[i];
        if (sz == 15)      W1 = (const float*)d_in[i];
        else if (sz == 35) W2 = (const float*)d_in[i];
        else if (sz == 63) W3 = (const float*)d_in[i];
        else { vech = (const float*)d_in[i]; vech_elems = sz; }
    }
    int B = vech_elems / 6;
    int nTiles = (B + 31) / 32;
    int grid = (nTiles + WPB - 1) / WPB;
    if (grid > MAXBLOCKS) grid = MAXBLOCKS;
    spd_main_kernel<<<grid, BLK>>>(vech, W1, W2, W3, (float*)d_out, B);
}